// round 16
// baseline (speedup 1.0000x reference)
#include <cuda_runtime.h>
#include <cuda_fp16.h>
#include <cstdint>

// Problem constants
#define NV_TOT 20000
#define IN_DIM 150
#define H_DIM  64
#define O_DIM  128
#define PT_DIM 80
#define CONN_STRIDE 240   // PT_DIM * 3

#define MTILE 64
#define NBLK  ((NV_TOT + MTILE - 1) / MTILE)   // 313

// SMEM layout (bytes from dynamic base)
#define OFF_BG  0                 // 128 floats
#define OFF_RS  512               // 64 floats
#define OFF_BUF 1024
// per buffer: A(8K) B(16K) = 24K
#define A_O     0
#define B_O     8192
#define BUF_STRIDE 24576
#define SMEM_TOTAL (1024 + 2 * BUF_STRIDE)   // 50176

// Scratch
__device__ __align__(16) __half   g_h16[NV_TOT * H_DIM];  // fp16 hidden, 2.56MB
__device__ __align__(16) uint32_t g_bf[PT_DIM * 4096];    // B fp16, fragment layout

// ---------------------------------------------------------------------------
__device__ __forceinline__ void mma16816(float* d, const uint32_t* a, const uint32_t* b) {
    asm volatile("mma.sync.aligned.m16n8k16.row.col.f32.f16.f16.f32 "
                 "{%0,%1,%2,%3}, {%4,%5,%6,%7}, {%8,%9}, {%0,%1,%2,%3};"
                 : "+f"(d[0]), "+f"(d[1]), "+f"(d[2]), "+f"(d[3])
                 : "r"(a[0]), "r"(a[1]), "r"(a[2]), "r"(a[3]),
                   "r"(b[0]), "r"(b[1]));
}

// ---------------------------------------------------------------------------
// prep B: Wg[o][h][pt] -> fp16, MMA fragment layout:
// word = ((ntile*4 + ks)*32 + gro*4 + q)*2 + r4
// ---------------------------------------------------------------------------
__global__ void __launch_bounds__(256) k_prepB(const float* __restrict__ Wg) {
    int b = blockIdx.x;
    int pt = b >> 2;
    int base = (b & 3) * 1024 + threadIdx.x;
#pragma unroll
    for (int i = 0; i < 4; i++) {
        int item = base + i * 256;            // item = o*32 + hp
        int o = item >> 5, hp = item & 31;
        float w0 = Wg[(o * H_DIM + 2 * hp) * PT_DIM + pt];
        float w1 = Wg[(o * H_DIM + 2 * hp + 1) * PT_DIM + pt];
        __half2 hh = __floats2half2_rn(w0, w1);
        int ntile = o >> 3, gro = o & 7;
        int ks = hp >> 3, r4 = (hp >> 2) & 1, q = hp & 3;
        int word = ((ntile * 4 + ks) * 32 + gro * 4 + q) * 2 + r4;
        g_bf[pt * 4096 + word] = *(uint32_t*)&hh;
    }
}

// ---------------------------------------------------------------------------
// h = relu(x @ W1^T) -> g_h16 (fp16)
// ---------------------------------------------------------------------------
__global__ void __launch_bounds__(256) k_hidden(const float* __restrict__ x,
                                                const float* __restrict__ W1) {
    __shared__ float W1t[IN_DIM * H_DIM];
    int t = threadIdx.x;
    for (int idx = t; idx < IN_DIM * H_DIM; idx += 256) {
        int i = idx >> 6, h = idx & 63;
        W1t[idx] = W1[h * IN_DIM + i];
    }
    __syncthreads();

    int vbase = blockIdx.x * 32;
    int h = t & 63;
    int vg = t >> 6;
    const float* xrow = x + (long)(vbase + vg * 8) * IN_DIM;
    float acc[8];
#pragma unroll
    for (int j = 0; j < 8; j++) acc[j] = 0.0f;
    for (int i = 0; i < IN_DIM; i += 2) {
        float w0 = W1t[i * H_DIM + h];
        float w1 = W1t[(i + 1) * H_DIM + h];
#pragma unroll
        for (int j = 0; j < 8; j++) {
            float2 xv = *(const float2*)(xrow + j * IN_DIM + i);
            acc[j] = fmaf(xv.x, w0, acc[j]);
            acc[j] = fmaf(xv.y, w1, acc[j]);
        }
    }
#pragma unroll
    for (int j = 0; j < 8; j++)
        g_h16[(long)(vbase + vg * 8 + j) * H_DIM + h] = __float2half(fmaxf(acc[j], 0.0f));
}

// ---------------------------------------------------------------------------
// Main: 64v M-tile (313 blocks), 512 threads (16 warps, warp tile 16x32),
// occ 2. Single-term fp16 mma.sync; fp16 gather. Pipeline per chunk c:
//   ldconn(c+2); ldgather(c+1) + ldB(c+1)  [all LDGs in flight]
//   mma(c)                                  [covers LDG latency]
//   stsB(c+1) + stsA(c+1)                   [pure smem stores]
//   one __syncthreads
// ---------------------------------------------------------------------------
__global__ void __launch_bounds__(512, 2) k_main(const int*   __restrict__ conn_idx,
                                                 const float* __restrict__ conn_w,
                                                 const float* __restrict__ bg,
                                                 float*       __restrict__ out) {
    extern __shared__ char smem_c[];
    float* s_bg = (float*)(smem_c + OFF_BG);
    float* s_rs = (float*)(smem_c + OFF_RS);

    int t = threadIdx.x;
    int wid = t >> 5, l = t & 31;
    int vbase = blockIdx.x * MTILE;

    if (t < 128) s_bg[t] = bg[t];
    if (t < MTILE) s_rs[t] = 0.0f;

    int mtile = wid & 3;       // m0 = mtile*16
    int nq = wid >> 2;         // n0 = nq*32
    int gr = l >> 2, q = l & 3;

    float acc[4][4];
#pragma unroll
    for (int a2 = 0; a2 < 4; a2++)
#pragma unroll
        for (int a3 = 0; a3 < 4; a3++) acc[a2][a3] = 0.0f;

    // conn loader: lanes 0..11 load idx, 12..23 load weights, for this warp's
    // 4 gather rows (wid + 16*i), chunk c. OOB rows -> 0.
    auto ldconn = [&](int c) -> uint32_t {
        uint32_t v = 0;
        if (l < 12) {
            int r = l / 3, k = l - 3 * r;
            int gv = vbase + wid + 16 * r;
            if (gv < NV_TOT)
                v = (uint32_t)conn_idx[(long)gv * CONN_STRIDE + c * 3 + k];
        } else if (l < 24) {
            int ll = l - 12;
            int r = ll / 3, k = ll - 3 * r;
            int gv = vbase + wid + 16 * r;
            if (gv < NV_TOT)
                v = __float_as_uint(conn_w[(long)gv * CONN_STRIDE + c * 3 + k]);
        }
        return v;
    };

    // issue the 12 gather LDGs (fp16 rows, one uint32 = half2 per lane)
    auto ldgather = [&](uint32_t connv, uint32_t* hv) {
#pragma unroll
        for (int i = 0; i < 4; i++) {
            int i0 = (int)__shfl_sync(0xffffffffu, connv, i * 3 + 0);
            int i1 = (int)__shfl_sync(0xffffffffu, connv, i * 3 + 1);
            int i2 = (int)__shfl_sync(0xffffffffu, connv, i * 3 + 2);
            hv[i * 3 + 0] = *((const uint32_t*)(g_h16 + (long)i0 * H_DIM) + l);
            hv[i * 3 + 1] = *((const uint32_t*)(g_h16 + (long)i1 * H_DIM) + l);
            hv[i * 3 + 2] = *((const uint32_t*)(g_h16 + (long)i2 * H_DIM) + l);
        }
    };

    // B tile LDGs -> registers (fragment layout, coalesced)
    auto ldB = [&](int c, float4* breg) {
        const float4* src = (const float4*)(g_bf + c * 4096);
        breg[0] = src[t];
        breg[1] = src[t + 512];
    };
    auto stsB = [&](const float4* breg, char* buf) {
        float4* dst = (float4*)(buf + B_O);
        dst[t]       = breg[0];
        dst[t + 512] = breg[1];
    };

    // combine + convert + store A into fragment layout
    auto stsA = [&](uint32_t connv, const uint32_t* hv, char* buf) {
#pragma unroll
        for (int i = 0; i < 4; i++) {
            float w0 = __uint_as_float(__shfl_sync(0xffffffffu, connv, 12 + i * 3 + 0));
            float w1 = __uint_as_float(__shfl_sync(0xffffffffu, connv, 12 + i * 3 + 1));
            float w2 = __uint_as_float(__shfl_sync(0xffffffffu, connv, 12 + i * 3 + 2));
            float2 h0 = __half22float2(*(const __half2*)&hv[i * 3 + 0]);
            float2 h1 = __half22float2(*(const __half2*)&hv[i * 3 + 1]);
            float2 h2 = __half22float2(*(const __half2*)&hv[i * 3 + 2]);
            float ax = fmaf(w2, h2.x, fmaf(w1, h1.x, w0 * h0.x));
            float ay = fmaf(w2, h2.y, fmaf(w1, h1.y, w0 * h0.y));
            __half2 hh = __floats2half2_rn(ax, ay);
            int vv = wid + 16 * i;
            int mt2 = vv >> 4, r = vv & 15, grv = r & 7, half = r >> 3;
            int ks = l >> 3, r4 = (l >> 2) & 1, qq = l & 3;
            int slot = (grv * 4 + qq) ^ ((ks * 5) & 31);
            int word = ((mt2 * 4 + ks) * 32 + slot) * 4 + r4 * 2 + half;
            ((uint32_t*)(buf + A_O))[word] = *(uint32_t*)&hh;
        }
    };

    auto mma_chunk = [&](int bsel) {
        const char* buf = smem_c + OFF_BUF + bsel * BUF_STRIDE;
#pragma unroll
        for (int ks = 0; ks < 4; ks++) {
            int aslot = l ^ ((ks * 5) & 31);
            uint4 aF = ((const uint4*)(buf + A_O))[(mtile * 4 + ks) * 32 + aslot];
            uint2 bF[4];
#pragma unroll
            for (int nt = 0; nt < 4; nt++)
                bF[nt] = ((const uint2*)(buf + B_O))[((nq * 4 + nt) * 4 + ks) * 32 + l];
#pragma unroll
            for (int nt = 0; nt < 4; nt++)
                mma16816(acc[nt], (const uint32_t*)&aF, (const uint32_t*)&bF[nt]);
        }
    };

    uint32_t hv[12];
    float4 breg[2];

    // prologue: chunk 0 staged directly; conn(1) in flight
    uint32_t conn0 = ldconn(0);
    uint32_t connNext = ldconn(1);
    ldgather(conn0, hv);
    ldB(0, breg);
    stsB(breg, smem_c + OFF_BUF);
    stsA(conn0, hv, smem_c + OFF_BUF);
    __syncthreads();

    for (int c = 0; c < PT_DIM; c++) {
        int bsel = c & 1;
        uint32_t connFut = (c + 2 < PT_DIM) ? ldconn(c + 2) : 0u;
        if (c + 1 < PT_DIM) {
            ldgather(connNext, hv);     // gather LDGs in flight...
            ldB(c + 1, breg);           // ...and B LDGs in flight...
        }
        mma_chunk(bsel);                // ...all covered by MMAs
        if (c + 1 < PT_DIM) {
            char* nbuf = smem_c + OFF_BUF + (bsel ^ 1) * BUF_STRIDE;
            stsB(breg, nbuf);           // pure smem stores post-MMA
            stsA(connNext, hv, nbuf);
        }
        connNext = connFut;
        __syncthreads();
    }

    // epilogue: bias, rowsums, L2-normalize, store
#pragma unroll
    for (int nt = 0; nt < 4; nt++)
#pragma unroll
        for (int p = 0; p < 4; p++)
            acc[nt][p] += s_bg[nq * 32 + nt * 8 + q * 2 + (p & 1)];

#pragma unroll
    for (int qh = 0; qh < 2; qh++) {
        float part = 0.f;
#pragma unroll
        for (int nt = 0; nt < 4; nt++) {
            float v0 = acc[nt][qh * 2 + 0];
            float v1 = acc[nt][qh * 2 + 1];
            part = fmaf(v0, v0, part);
            part = fmaf(v1, v1, part);
        }
        part += __shfl_xor_sync(0xffffffffu, part, 1);
        part += __shfl_xor_sync(0xffffffffu, part, 2);
        if (q == 0) atomicAdd(&s_rs[mtile * 16 + gr + qh * 8], part);
    }
    __syncthreads();

#pragma unroll
    for (int qh = 0; qh < 2; qh++) {
        int row = mtile * 16 + gr + qh * 8;
        int row_g = vbase + row;
        if (row_g < NV_TOT) {
            float inv = rsqrtf(s_rs[row]);
#pragma unroll
            for (int nt = 0; nt < 4; nt++) {
                float2 o2;
                o2.x = acc[nt][qh * 2 + 0] * inv;
                o2.y = acc[nt][qh * 2 + 1] * inv;
                *(float2*)&out[(long)row_g * O_DIM + nq * 32 + nt * 8 + q * 2] = o2;
            }
        }
    }
}

// ---------------------------------------------------------------------------
extern "C" void kernel_launch(void* const* d_in, const int* in_sizes, int n_in,
                              void* d_out, int out_size) {
    const float* x    = (const float*)d_in[0];
    const int*   cidx = (const int*)d_in[1];
    const float* cw   = (const float*)d_in[2];
    const float* W1   = (const float*)d_in[3];
    const float* Wg   = (const float*)d_in[4];
    const float* bg   = (const float*)d_in[5];
    float* out = (float*)d_out;

    cudaFuncSetAttribute(k_main, cudaFuncAttributeMaxDynamicSharedMemorySize,
                         SMEM_TOTAL);

    k_prepB<<<PT_DIM * 4, 256>>>(Wg);
    k_hidden<<<NV_TOT / 32, 256>>>(x, W1);
    k_main<<<NBLK, 512, SMEM_TOTAL>>>(cidx, cw, bg, out);
}

// round 17
// speedup vs baseline: 1.8526x; 1.8526x over previous
#include <cuda_runtime.h>
#include <cuda_fp16.h>
#include <cstdint>

// Problem constants
#define NV_TOT 20000
#define IN_DIM 150
#define H_DIM  64
#define O_DIM  128
#define PT_DIM 80
#define CONN_STRIDE 240   // PT_DIM * 3

#define MTILE 48
#define NBLK  444          // 3 * 148 SMs: perfectly balanced; 444*48 >= 20000
#define NTHR  384          // 12 warps: mtile (3) x nq (4)

// SMEM layout (bytes from dynamic base)
#define OFF_BG  0                 // 128 floats
#define OFF_RS  512               // 48 floats
#define OFF_BUF 1024
// per buffer: A(6K) B(16K)
#define A_O     0
#define B_O     6144
#define BUF_STRIDE 22528
#define SMEM_TOTAL (1024 + 2 * BUF_STRIDE)   // 46080 -> occ 3 (138KB/SM)

// Scratch
__device__ __align__(16) __half   g_h16[NV_TOT * H_DIM];  // fp16 hidden, 2.56MB
__device__ __align__(16) uint32_t g_bf[PT_DIM * 4096];    // B fp16, fragment layout

// ---------------------------------------------------------------------------
__device__ __forceinline__ void mma16816(float* d, const uint32_t* a, const uint32_t* b) {
    asm volatile("mma.sync.aligned.m16n8k16.row.col.f32.f16.f16.f32 "
                 "{%0,%1,%2,%3}, {%4,%5,%6,%7}, {%8,%9}, {%0,%1,%2,%3};"
                 : "+f"(d[0]), "+f"(d[1]), "+f"(d[2]), "+f"(d[3])
                 : "r"(a[0]), "r"(a[1]), "r"(a[2]), "r"(a[3]),
                   "r"(b[0]), "r"(b[1]));
}

// ---------------------------------------------------------------------------
// prep B: Wg[o][h][pt] -> fp16, MMA fragment layout:
// word = ((ntile*4 + ks)*32 + gro*4 + q)*2 + r4
// ---------------------------------------------------------------------------
__global__ void __launch_bounds__(256) k_prepB(const float* __restrict__ Wg) {
    int b = blockIdx.x;
    int pt = b >> 2;
    int base = (b & 3) * 1024 + threadIdx.x;
#pragma unroll
    for (int i = 0; i < 4; i++) {
        int item = base + i * 256;            // item = o*32 + hp
        int o = item >> 5, hp = item & 31;
        float w0 = Wg[(o * H_DIM + 2 * hp) * PT_DIM + pt];
        float w1 = Wg[(o * H_DIM + 2 * hp + 1) * PT_DIM + pt];
        __half2 hh = __floats2half2_rn(w0, w1);
        int ntile = o >> 3, gro = o & 7;
        int ks = hp >> 3, r4 = (hp >> 2) & 1, q = hp & 3;
        int word = ((ntile * 4 + ks) * 32 + gro * 4 + q) * 2 + r4;
        g_bf[pt * 4096 + word] = *(uint32_t*)&hh;
    }
}

// ---------------------------------------------------------------------------
// h = relu(x @ W1^T) -> g_h16 (fp16)
// ---------------------------------------------------------------------------
__global__ void __launch_bounds__(256) k_hidden(const float* __restrict__ x,
                                                const float* __restrict__ W1) {
    __shared__ float W1t[IN_DIM * H_DIM];
    int t = threadIdx.x;
    for (int idx = t; idx < IN_DIM * H_DIM; idx += 256) {
        int i = idx >> 6, h = idx & 63;
        W1t[idx] = W1[h * IN_DIM + i];
    }
    __syncthreads();

    int vbase = blockIdx.x * 32;
    int h = t & 63;
    int vg = t >> 6;
    const float* xrow = x + (long)(vbase + vg * 8) * IN_DIM;
    float acc[8];
#pragma unroll
    for (int j = 0; j < 8; j++) acc[j] = 0.0f;
    for (int i = 0; i < IN_DIM; i += 2) {
        float w0 = W1t[i * H_DIM + h];
        float w1 = W1t[(i + 1) * H_DIM + h];
#pragma unroll
        for (int j = 0; j < 8; j++) {
            float2 xv = *(const float2*)(xrow + j * IN_DIM + i);
            acc[j] = fmaf(xv.x, w0, acc[j]);
            acc[j] = fmaf(xv.y, w1, acc[j]);
        }
    }
#pragma unroll
    for (int j = 0; j < 8; j++)
        g_h16[(long)(vbase + vg * 8 + j) * H_DIM + h] = __float2half(fmaxf(acc[j], 0.0f));
}

// ---------------------------------------------------------------------------
// Main: 48v M-tile, 444 blocks = 3 per SM exactly (zero imbalance), 384
// threads (12 warps, warp tile 16x32: mtile=wid%3, nq=wid/3), occ 3.
// Single-term fp16 mma.sync; fp16 gather; conn prefetch depth 2; gather LDGs
// issued before mma(c); B staged LDG->STS after mma (R13-proven ordering).
// ---------------------------------------------------------------------------
__global__ void __launch_bounds__(NTHR, 3) k_main(const int*   __restrict__ conn_idx,
                                                  const float* __restrict__ conn_w,
                                                  const float* __restrict__ bg,
                                                  float*       __restrict__ out) {
    extern __shared__ char smem_c[];
    float* s_bg = (float*)(smem_c + OFF_BG);
    float* s_rs = (float*)(smem_c + OFF_RS);

    int t = threadIdx.x;
    int wid = t >> 5, l = t & 31;
    int vbase = blockIdx.x * MTILE;

    if (t < 128) s_bg[t] = bg[t];
    if (t < MTILE) s_rs[t] = 0.0f;

    int mtile = wid % 3;       // m0 = mtile*16 (3 m-tiles)
    int nq = wid / 3;          // n0 = nq*32   (4 n-quads)
    int gr = l >> 2, q = l & 3;

    float acc[4][4];
#pragma unroll
    for (int a2 = 0; a2 < 4; a2++)
#pragma unroll
        for (int a3 = 0; a3 < 4; a3++) acc[a2][a3] = 0.0f;

    // conn loader: lanes 0..11 load idx, 12..23 load weights, for this warp's
    // 4 gather rows (wid + 12*r), chunk c. OOB rows -> 0.
    auto ldconn = [&](int c) -> uint32_t {
        uint32_t v = 0;
        if (l < 12) {
            int r = l / 3, k = l - 3 * r;
            int gv = vbase + wid + 12 * r;
            if (gv < NV_TOT)
                v = (uint32_t)conn_idx[(long)gv * CONN_STRIDE + c * 3 + k];
        } else if (l < 24) {
            int ll = l - 12;
            int r = ll / 3, k = ll - 3 * r;
            int gv = vbase + wid + 12 * r;
            if (gv < NV_TOT)
                v = __float_as_uint(conn_w[(long)gv * CONN_STRIDE + c * 3 + k]);
        }
        return v;
    };

    // issue the 12 gather LDGs (fp16 rows, one uint32 = half2 per lane)
    auto ldgather = [&](uint32_t connv, uint32_t* hv) {
#pragma unroll
        for (int i = 0; i < 4; i++) {
            int i0 = (int)__shfl_sync(0xffffffffu, connv, i * 3 + 0);
            int i1 = (int)__shfl_sync(0xffffffffu, connv, i * 3 + 1);
            int i2 = (int)__shfl_sync(0xffffffffu, connv, i * 3 + 2);
            hv[i * 3 + 0] = *((const uint32_t*)(g_h16 + (long)i0 * H_DIM) + l);
            hv[i * 3 + 1] = *((const uint32_t*)(g_h16 + (long)i1 * H_DIM) + l);
            hv[i * 3 + 2] = *((const uint32_t*)(g_h16 + (long)i2 * H_DIM) + l);
        }
    };

    // B tile: direct coalesced LDG->STS (fragment layout), 16KB / 384 threads
    auto stageB = [&](int c, char* buf) {
        const float4* src = (const float4*)(g_bf + c * 4096);
        float4* dst = (float4*)(buf + B_O);
#pragma unroll
        for (int j = 0; j < 3; j++) {
            int e = t + j * NTHR;
            if (e < 1024) dst[e] = src[e];
        }
    };

    // combine + convert + store A into fragment layout
    auto stsA = [&](uint32_t connv, const uint32_t* hv, char* buf) {
#pragma unroll
        for (int i = 0; i < 4; i++) {
            float w0 = __uint_as_float(__shfl_sync(0xffffffffu, connv, 12 + i * 3 + 0));
            float w1 = __uint_as_float(__shfl_sync(0xffffffffu, connv, 12 + i * 3 + 1));
            float w2 = __uint_as_float(__shfl_sync(0xffffffffu, connv, 12 + i * 3 + 2));
            float2 h0 = __half22float2(*(const __half2*)&hv[i * 3 + 0]);
            float2 h1 = __half22float2(*(const __half2*)&hv[i * 3 + 1]);
            float2 h2 = __half22float2(*(const __half2*)&hv[i * 3 + 2]);
            float ax = fmaf(w2, h2.x, fmaf(w1, h1.x, w0 * h0.x));
            float ay = fmaf(w2, h2.y, fmaf(w1, h1.y, w0 * h0.y));
            __half2 hh = __floats2half2_rn(ax, ay);
            int vv = wid + 12 * i;
            int mt2 = vv >> 4, r = vv & 15, grv = r & 7, half = r >> 3;
            int ks = l >> 3, r4 = (l >> 2) & 1, qq = l & 3;
            int slot = (grv * 4 + qq) ^ ((ks * 5) & 31);
            int word = ((mt2 * 4 + ks) * 32 + slot) * 4 + r4 * 2 + half;
            ((uint32_t*)(buf + A_O))[word] = *(uint32_t*)&hh;
        }
    };

    auto mma_chunk = [&](int bsel) {
        const char* buf = smem_c + OFF_BUF + bsel * BUF_STRIDE;
#pragma unroll
        for (int ks = 0; ks < 4; ks++) {
            int aslot = l ^ ((ks * 5) & 31);
            uint4 aF = ((const uint4*)(buf + A_O))[(mtile * 4 + ks) * 32 + aslot];
            uint2 bF[4];
#pragma unroll
            for (int nt = 0; nt < 4; nt++)
                bF[nt] = ((const uint2*)(buf + B_O))[((nq * 4 + nt) * 4 + ks) * 32 + l];
#pragma unroll
            for (int nt = 0; nt < 4; nt++)
                mma16816(acc[nt], (const uint32_t*)&aF, (const uint32_t*)&bF[nt]);
        }
    };

    uint32_t hv[12];

    // prologue: chunk 0 staged directly; conn(1) in flight
    uint32_t conn0 = ldconn(0);
    uint32_t connNext = ldconn(1);
    ldgather(conn0, hv);
    stageB(0, smem_c + OFF_BUF);
    stsA(conn0, hv, smem_c + OFF_BUF);
    __syncthreads();

    for (int c = 0; c < PT_DIM; c++) {
        int bsel = c & 1;
        uint32_t connFut = (c + 2 < PT_DIM) ? ldconn(c + 2) : 0u;
        if (c + 1 < PT_DIM) ldgather(connNext, hv);   // gather LDGs in flight...
        mma_chunk(bsel);                              // ...covered by MMAs
        if (c + 1 < PT_DIM) {
            char* nbuf = smem_c + OFF_BUF + (bsel ^ 1) * BUF_STRIDE;
            stageB(c + 1, nbuf);
            stsA(connNext, hv, nbuf);
        }
        connNext = connFut;
        __syncthreads();
    }

    // epilogue: bias, rowsums, L2-normalize, store
#pragma unroll
    for (int nt = 0; nt < 4; nt++)
#pragma unroll
        for (int p = 0; p < 4; p++)
            acc[nt][p] += s_bg[nq * 32 + nt * 8 + q * 2 + (p & 1)];

#pragma unroll
    for (int qh = 0; qh < 2; qh++) {
        float part = 0.f;
#pragma unroll
        for (int nt = 0; nt < 4; nt++) {
            float v0 = acc[nt][qh * 2 + 0];
            float v1 = acc[nt][qh * 2 + 1];
            part = fmaf(v0, v0, part);
            part = fmaf(v1, v1, part);
        }
        part += __shfl_xor_sync(0xffffffffu, part, 1);
        part += __shfl_xor_sync(0xffffffffu, part, 2);
        if (q == 0) atomicAdd(&s_rs[mtile * 16 + gr + qh * 8], part);
    }
    __syncthreads();

#pragma unroll
    for (int qh = 0; qh < 2; qh++) {
        int row = mtile * 16 + gr + qh * 8;
        int row_g = vbase + row;
        if (row_g < NV_TOT) {
            float inv = rsqrtf(s_rs[row]);
#pragma unroll
            for (int nt = 0; nt < 4; nt++) {
                float2 o2;
                o2.x = acc[nt][qh * 2 + 0] * inv;
                o2.y = acc[nt][qh * 2 + 1] * inv;
                *(float2*)&out[(long)row_g * O_DIM + nq * 32 + nt * 8 + q * 2] = o2;
            }
        }
    }
}

// ---------------------------------------------------------------------------
extern "C" void kernel_launch(void* const* d_in, const int* in_sizes, int n_in,
                              void* d_out, int out_size) {
    const float* x    = (const float*)d_in[0];
    const int*   cidx = (const int*)d_in[1];
    const float* cw   = (const float*)d_in[2];
    const float* W1   = (const float*)d_in[3];
    const float* Wg   = (const float*)d_in[4];
    const float* bg   = (const float*)d_in[5];
    float* out = (float*)d_out;

    cudaFuncSetAttribute(k_main, cudaFuncAttributeMaxDynamicSharedMemorySize,
                         SMEM_TOTAL);

    k_prepB<<<PT_DIM * 4, 256>>>(Wg);
    k_hidden<<<NV_TOT / 32, 256>>>(x, W1);
    k_main<<<NBLK, NTHR, SMEM_TOTAL>>>(cidx, cw, bg, out);
}